// round 6
// baseline (speedup 1.0000x reference)
#include <cuda_runtime.h>
#include <cstdint>

// ---------------------------------------------------------------------------
// ChannelMultiHeadAttention, fp32 in/out, tf32 tensor-core compute.
//   energy = x A x^T + xu1 1^T + 1 xu2^T + c0,  A = Wq^T Wk
//   out    = (att @ x) Wv^T + bv
// R6: xu1/xu2 folded into Y GEMM as extra A columns (64x72);
//     11 warps/CTA -> 22 warps/SM.
// ---------------------------------------------------------------------------

#define FULLMASK 0xffffffffu

__device__ float g_Ax[4608];   // [d][e] stride 72: A = Wq^T Wk (cols 0-63),
                               // col 64 = u1 = Wq^T bk, col 65 = u2 = Wk^T bq, 66-71 = 0
__device__ float g_W[4096];    // W[d][e] = Wv[e][d], tf32-rounded
__device__ float g_wc[256];    // w_c padded 16x16, tf32-rounded (pad = 0)
__device__ float g_c0[1];

__device__ __forceinline__ uint32_t tf32r(float f) {
    uint32_t u; asm("cvt.rna.tf32.f32 %0, %1;" : "=r"(u) : "f"(f)); return u;
}
__device__ __forceinline__ float tf32f(float f) { return __uint_as_float(tf32r(f)); }
__device__ __forceinline__ uint32_t fbits(float f) { return __float_as_uint(f); }

__device__ __forceinline__ void mma8(float* d, uint32_t a0, uint32_t a1, uint32_t a2,
                                     uint32_t a3, uint32_t b0, uint32_t b1) {
    asm("mma.sync.aligned.m16n8k8.row.col.f32.tf32.tf32.f32 "
        "{%0,%1,%2,%3}, {%4,%5,%6,%7}, {%8,%9}, {%0,%1,%2,%3};"
        : "+f"(d[0]), "+f"(d[1]), "+f"(d[2]), "+f"(d[3])
        : "r"(a0), "r"(a1), "r"(a2), "r"(a3), "r"(b0), "r"(b1));
}

// ---------------------------------------------------------------------------
__global__ void prep_kernel(const float* __restrict__ Wq, const float* __restrict__ bq,
                            const float* __restrict__ Wk, const float* __restrict__ bk,
                            const float* __restrict__ Wv, const float* __restrict__ wc) {
    __shared__ float sWq[4096], sWk[4096];
    int t = threadIdx.x;
    for (int i = t; i < 4096; i += 256) { sWq[i] = Wq[i]; sWk[i] = Wk[i]; }
    __syncthreads();
    for (int idx = t; idx < 4096; idx += 256) {
        int d = idx >> 6, e = idx & 63;
        float a = 0.f;
        #pragma unroll 8
        for (int f = 0; f < 64; f++) a += sWq[f * 64 + d] * sWk[f * 64 + e];
        g_Ax[d * 72 + e] = tf32f(a);
        g_W[idx] = tf32f(Wv[e * 64 + d]);   // W[d][e] = Wv[e][d]
    }
    if (t < 256) {
        int a = t >> 4, c = t & 15;
        float v = (a < 14 && c < 14) ? wc[a * 14 + c] : 0.f;
        g_wc[t] = tf32f(v);
    }
    if (t < 64) {
        float s1 = 0.f, s2 = 0.f;
        for (int f = 0; f < 64; f++) {
            s1 += sWq[f * 64 + t] * bk[f];
            s2 += sWk[f * 64 + t] * bq[f];
        }
        g_Ax[t * 72 + 64] = tf32f(s1);
        g_Ax[t * 72 + 65] = tf32f(s2);
        g_Ax[t * 72 + 66] = 0.f; g_Ax[t * 72 + 67] = 0.f;
        g_Ax[t * 72 + 68] = 0.f; g_Ax[t * 72 + 69] = 0.f;
        g_Ax[t * 72 + 70] = 0.f; g_Ax[t * 72 + 71] = 0.f;
    }
    if (t == 0) {
        float c = 0.f;
        for (int f = 0; f < 64; f++) c += bq[f] * bk[f];
        g_c0[0] = c;
    }
}

// ---------------------------------------------------------------------------
// Main: 1 warp = 1 pair, 11 warps/CTA.
// Per-warp smem: x tile 16x68 + 32 (xu).  Shared: sA/sW stride 72, w_c stride 20.
// ---------------------------------------------------------------------------
static const int NW = 11;
static const int SMEM_FLOATS = 9632 + NW * 1120;   // 21952 fl = 87808 B
static const int NPAIRS = 65536;

__global__ __launch_bounds__(32 * NW, 2)
void attn_kernel(const float* __restrict__ x, const float* __restrict__ bv,
                 const float* __restrict__ lng, const float* __restrict__ lnb,
                 float* __restrict__ out) {
    extern __shared__ float sf[];
    float* sA  = sf;            // 64 x 72 (incl. u1/u2 cols)
    float* sW  = sf + 4608;     // 64 x 72
    float* swc = sf + 9216;     // 16 x 20
    float* sbv = sf + 9536;
    float* slg = sf + 9600;
    float* slb = sf + 9616;     // per-warp tiles start at 9632

    const int t = threadIdx.x, w = t >> 5, l = t & 31;
    const int g = l >> 2, tg = l & 3;

    for (int i = t; i < 4608; i += 32 * NW) sA[i] = g_Ax[i];
    for (int i = t; i < 4096; i += 32 * NW) {
        int d = i >> 6, e = i & 63;
        sW[d * 72 + e] = g_W[i];
    }
    if (t < 256) { int a = t >> 4, c = t & 15; swc[a * 20 + c] = g_wc[t]; }
    if (t < 64) sbv[t] = bv[t];
    if (t < 16) {
        slg[t] = (t < 14) ? lng[t] : 0.f;
        slb[t] = (t < 14) ? lnb[t] : 0.f;
    }
    __syncthreads();

    const size_t pair = (size_t)blockIdx.x * NW + w;
    if (pair >= NPAIRS) return;
    const float c0 = g_c0[0];

    float* sx   = sf + 9632 + w * 1120;   // 16 x 68
    float* sxu1 = sx + 1088;              // 16
    float* sxu2 = sx + 1104;              // 16

    // ---- load x tile, round to tf32, zero pad rows 14/15 ----
    const float4* xg4 = (const float4*)(x + pair * 896);
    #pragma unroll
    for (int it = 0; it < 7; it++) {
        int k = l + 32 * it;
        float4 v = xg4[k];
        int row = k >> 4, c = (k & 15) << 2;
        *(float4*)(sx + row * 68 + c) =
            make_float4(tf32f(v.x), tf32f(v.y), tf32f(v.z), tf32f(v.w));
    }
    if (l < 16) {
        float4 z4 = make_float4(0.f, 0.f, 0.f, 0.f);
        *(float4*)(sx + 14 * 68 + 4 * l) = z4;
        *(float4*)(sx + 15 * 68 + 4 * l) = z4;
    }
    __syncwarp();

    const int srcA = 4 * g + (tg >> 1);   // quad-local relayout sources
    const int srcB = srcA + 2;
    const bool pr = tg & 1;

    // ---- Y = x @ [A | u1 u2]  (M16 N72 K64: 72 MMAs), results in regs ----
    float dY[9][4] = {};
    #pragma unroll
    for (int k0 = 0; k0 < 8; k0++) {
        uint32_t a0 = fbits(sx[g * 68 + k0 * 8 + tg]);
        uint32_t a1 = fbits(sx[(g + 8) * 68 + k0 * 8 + tg]);
        uint32_t a2 = fbits(sx[g * 68 + k0 * 8 + tg + 4]);
        uint32_t a3 = fbits(sx[(g + 8) * 68 + k0 * 8 + tg + 4]);
        #pragma unroll
        for (int n0 = 0; n0 < 9; n0++) {
            uint32_t b0 = fbits(sA[(k0 * 8 + tg) * 72 + n0 * 8 + g]);
            uint32_t b1 = fbits(sA[(k0 * 8 + tg + 4) * 72 + n0 * 8 + g]);
            mma8(dY[n0], a0, a1, a2, a3, b0, b1);
        }
    }
    // dY[8]: cols 64-71; tg==0 lanes hold (xu1, xu2) for rows g, g+8
    if (tg == 0) {
        sxu1[g] = dY[8][0]; sxu2[g] = dY[8][1];
        sxu1[g + 8] = dY[8][2]; sxu2[g + 8] = dY[8][3];
    }
    // pre-round y to tf32 (same rounding point as smem store would be)
    #pragma unroll
    for (int n0 = 0; n0 < 8; n0++)
        #pragma unroll
        for (int j = 0; j < 4; j++) dY[n0][j] = tf32f(dY[n0][j]);

    // ---- energy = y @ x^T + biases  (16 MMAs); y A-frags via shuffle ----
    float et[2][4];
    {
        float e[2][4] = {};
        #pragma unroll
        for (int k0 = 0; k0 < 8; k0++) {
            float v0 = __shfl_sync(FULLMASK, dY[k0][0], srcA);
            float v1 = __shfl_sync(FULLMASK, dY[k0][1], srcA);
            float v2 = __shfl_sync(FULLMASK, dY[k0][2], srcA);
            float v3 = __shfl_sync(FULLMASK, dY[k0][3], srcA);
            float w0 = __shfl_sync(FULLMASK, dY[k0][0], srcB);
            float w1 = __shfl_sync(FULLMASK, dY[k0][1], srcB);
            float w2 = __shfl_sync(FULLMASK, dY[k0][2], srcB);
            float w3 = __shfl_sync(FULLMASK, dY[k0][3], srcB);
            uint32_t a0 = fbits(pr ? v1 : v0);
            uint32_t a1 = fbits(pr ? v3 : v2);
            uint32_t a2 = fbits(pr ? w1 : w0);
            uint32_t a3 = fbits(pr ? w3 : w2);
            #pragma unroll
            for (int nt = 0; nt < 2; nt++) {
                uint32_t b0 = fbits(sx[(nt * 8 + g) * 68 + k0 * 8 + tg]);
                uint32_t b1 = fbits(sx[(nt * 8 + g) * 68 + k0 * 8 + tg + 4]);
                mma8(e[nt], a0, a1, a2, a3, b0, b1);
            }
        }
        __syncwarp();   // sxu1/sxu2 stores visible
        float xg0 = sxu1[g] + c0, xg8 = sxu1[g + 8] + c0;
        #pragma unroll
        for (int nt = 0; nt < 2; nt++) {
            int j0 = nt * 8 + 2 * tg;
            float u0 = sxu2[j0], u1v = sxu2[j0 + 1];
            et[nt][0] = tf32f(e[nt][0] + xg0 + u0);
            et[nt][1] = tf32f(e[nt][1] + xg0 + u1v);
            et[nt][2] = tf32f(e[nt][2] + xg8 + u0);
            et[nt][3] = tf32f(e[nt][3] + xg8 + u1v);
        }
    }

    // ---- mix = w_c @ energy (4 MMAs); energy B-frags via shuffle ----
    float att0[2], att1[2], att2[2], att3[2];
    {
        const int srcM  = 4 * tg + (g >> 1);       // row 8k0+tg source
        const int srcM4 = 16 + 4 * tg + (g >> 1);  // row 8k0+tg+4 source
        const bool pg = g & 1;
        float m[2][4] = {};
        #pragma unroll
        for (int k0 = 0; k0 < 2; k0++) {
            uint32_t a0 = fbits(swc[g * 20 + k0 * 8 + tg]);
            uint32_t a1 = fbits(swc[(g + 8) * 20 + k0 * 8 + tg]);
            uint32_t a2 = fbits(swc[g * 20 + k0 * 8 + tg + 4]);
            uint32_t a3 = fbits(swc[(g + 8) * 20 + k0 * 8 + tg + 4]);
            #pragma unroll
            for (int nt = 0; nt < 2; nt++) {
                float v0 = __shfl_sync(FULLMASK, et[nt][2 * k0], srcM);
                float v1 = __shfl_sync(FULLMASK, et[nt][2 * k0 + 1], srcM);
                float w0 = __shfl_sync(FULLMASK, et[nt][2 * k0], srcM4);
                float w1 = __shfl_sync(FULLMASK, et[nt][2 * k0 + 1], srcM4);
                uint32_t b0 = fbits(pg ? v1 : v0);
                uint32_t b1 = fbits(pg ? w1 : w0);
                mma8(m[nt], a0, a1, a2, a3, b0, b1);
            }
        }
        // ---- LayerNorm + softmax in regs (quad reductions) ----
        const bool m3 = (tg == 3);   // cols 14,15
        float lg0 = slg[2 * tg], lg1 = slg[2 * tg + 1];
        float lg2 = slg[8 + 2 * tg], lg3 = slg[9 + 2 * tg];
        float lb0 = slb[2 * tg], lb1 = slb[2 * tg + 1];
        float lb2 = slb[8 + 2 * tg], lb3 = slb[9 + 2 * tg];
        #pragma unroll
        for (int rr = 0; rr < 2; rr++) {
            float v0 = m[0][2 * rr], v1 = m[0][2 * rr + 1];
            float v2 = m[1][2 * rr], v3 = m[1][2 * rr + 1];
            float s = v0 + v1 + (m3 ? 0.f : (v2 + v3));
            s += __shfl_xor_sync(FULLMASK, s, 1);
            s += __shfl_xor_sync(FULLMASK, s, 2);
            float mu = s * (1.f / 14.f);
            float d0 = v0 - mu, d1 = v1 - mu, d2 = v2 - mu, d3 = v3 - mu;
            float q = d0 * d0 + d1 * d1 + (m3 ? 0.f : (d2 * d2 + d3 * d3));
            q += __shfl_xor_sync(FULLMASK, q, 1);
            q += __shfl_xor_sync(FULLMASK, q, 2);
            float rsv = rsqrtf(q * (1.f / 14.f) + 1e-5f);
            float t0 = (d0 * rsv * lg0 + lb0) * 0.125f;
            float t1 = (d1 * rsv * lg1 + lb1) * 0.125f;
            float t2 = (d2 * rsv * lg2 + lb2) * 0.125f;
            float t3 = (d3 * rsv * lg3 + lb3) * 0.125f;
            float mx = fmaxf(fmaxf(t0, t1), m3 ? -1e30f : fmaxf(t2, t3));
            mx = fmaxf(mx, __shfl_xor_sync(FULLMASK, mx, 1));
            mx = fmaxf(mx, __shfl_xor_sync(FULLMASK, mx, 2));
            float e0 = __expf(t0 - mx), e1 = __expf(t1 - mx);
            float e2 = m3 ? 0.f : __expf(t2 - mx);
            float e3 = m3 ? 0.f : __expf(t3 - mx);
            float ss = e0 + e1 + e2 + e3;
            ss += __shfl_xor_sync(FULLMASK, ss, 1);
            ss += __shfl_xor_sync(FULLMASK, ss, 2);
            float inv = 1.f / ss;
            att0[rr] = tf32f(e0 * inv); att1[rr] = tf32f(e1 * inv);
            att2[rr] = tf32f(e2 * inv); att3[rr] = tf32f(e3 * inv);
        }
    }

    // ---- z = att @ x  (16 MMAs); att A-frags via shuffle ----
    float zd[8][4] = {};
    #pragma unroll
    for (int k0 = 0; k0 < 2; k0++) {
        float p0, p1, q0, q1, p2, p3, q2, q3;
        if (k0 == 0) {
            p0 = __shfl_sync(FULLMASK, att0[0], srcA);
            p1 = __shfl_sync(FULLMASK, att1[0], srcA);
            p2 = __shfl_sync(FULLMASK, att0[1], srcA);
            p3 = __shfl_sync(FULLMASK, att1[1], srcA);
            q0 = __shfl_sync(FULLMASK, att0[0], srcB);
            q1 = __shfl_sync(FULLMASK, att1[0], srcB);
            q2 = __shfl_sync(FULLMASK, att0[1], srcB);
            q3 = __shfl_sync(FULLMASK, att1[1], srcB);
        } else {
            p0 = __shfl_sync(FULLMASK, att2[0], srcA);
            p1 = __shfl_sync(FULLMASK, att3[0], srcA);
            p2 = __shfl_sync(FULLMASK, att2[1], srcA);
            p3 = __shfl_sync(FULLMASK, att3[1], srcA);
            q0 = __shfl_sync(FULLMASK, att2[0], srcB);
            q1 = __shfl_sync(FULLMASK, att3[0], srcB);
            q2 = __shfl_sync(FULLMASK, att2[1], srcB);
            q3 = __shfl_sync(FULLMASK, att3[1], srcB);
        }
        uint32_t a0 = fbits(pr ? p1 : p0);
        uint32_t a1 = fbits(pr ? p3 : p2);
        uint32_t a2 = fbits(pr ? q1 : q0);
        uint32_t a3 = fbits(pr ? q3 : q2);
        #pragma unroll
        for (int n0 = 0; n0 < 8; n0++) {
            uint32_t b0 = fbits(sx[(k0 * 8 + tg) * 68 + n0 * 8 + g]);
            uint32_t b1 = fbits(sx[(k0 * 8 + tg + 4) * 68 + n0 * 8 + g]);
            mma8(zd[n0], a0, a1, a2, a3, b0, b1);
        }
    }
    __syncwarp();   // all x reads done; reuse sx for z
    #pragma unroll
    for (int n0 = 0; n0 < 8; n0++) {
        *(float2*)(sx + g * 68 + n0 * 8 + 2 * tg) =
            make_float2(tf32f(zd[n0][0]), tf32f(zd[n0][1]));
        *(float2*)(sx + (g + 8) * 68 + n0 * 8 + 2 * tg) =
            make_float2(tf32f(zd[n0][2]), tf32f(zd[n0][3]));
    }
    __syncwarp();

    // ---- out = z @ Wv^T + bv  (64 MMAs) ----
    {
        float od[8][4] = {};
        #pragma unroll
        for (int k0 = 0; k0 < 8; k0++) {
            uint32_t a0 = fbits(sx[g * 68 + k0 * 8 + tg]);
            uint32_t a1 = fbits(sx[(g + 8) * 68 + k0 * 8 + tg]);
            uint32_t a2 = fbits(sx[g * 68 + k0 * 8 + tg + 4]);
            uint32_t a3 = fbits(sx[(g + 8) * 68 + k0 * 8 + tg + 4]);
            #pragma unroll
            for (int n0 = 0; n0 < 8; n0++) {
                uint32_t b0 = fbits(sW[(k0 * 8 + tg) * 72 + n0 * 8 + g]);
                uint32_t b1 = fbits(sW[(k0 * 8 + tg + 4) * 72 + n0 * 8 + g]);
                mma8(od[n0], a0, a1, a2, a3, b0, b1);
            }
        }
        float* og = out + pair * 896;
        #pragma unroll
        for (int n0 = 0; n0 < 8; n0++) {
            int cc = n0 * 8 + 2 * tg;
            float2 bb = *(const float2*)(sbv + cc);
            *(float2*)(og + g * 64 + cc) =
                make_float2(od[n0][0] + bb.x, od[n0][1] + bb.y);
            if (g < 6)
                *(float2*)(og + (g + 8) * 64 + cc) =
                    make_float2(od[n0][2] + bb.x, od[n0][3] + bb.y);
        }
    }
}

// ---------------------------------------------------------------------------
extern "C" void kernel_launch(void* const* d_in, const int* in_sizes, int n_in,
                              void* d_out, int out_size) {
    const float* x   = (const float*)d_in[0];
    const float* wc  = (const float*)d_in[1];
    const float* Wq  = (const float*)d_in[2];
    const float* bq  = (const float*)d_in[3];
    const float* Wk  = (const float*)d_in[4];
    const float* bk  = (const float*)d_in[5];
    const float* Wv  = (const float*)d_in[6];
    const float* bv  = (const float*)d_in[7];
    const float* lng = (const float*)d_in[8];
    const float* lnb = (const float*)d_in[9];
    float* out = (float*)d_out;

    cudaFuncSetAttribute(attn_kernel, cudaFuncAttributeMaxDynamicSharedMemorySize,
                         SMEM_FLOATS * 4);

    prep_kernel<<<1, 256>>>(Wq, bq, Wk, bk, Wv, wc);
    int nblk = (NPAIRS + NW - 1) / NW;
    attn_kernel<<<nblk, 32 * NW, SMEM_FLOATS * 4>>>(x, bv, lng, lnb, out);
}